// round 1
// baseline (speedup 1.0000x reference)
#include <cuda_runtime.h>
#include <math.h>

// Problem constants
#define BB 4096          // batch
#define CC 32000         // classes
#define NV4 8000         // float4 per row (CC/4)
#define NT 1024          // threads per block in main kernel
#define KPT 8            // float4 slots per thread (NT*KPT*4 >= CC)
#define MAXGRID 160      // upper bound on persistent grid (>= SM count)

// Device scratch (static allocation — no cudaMalloc allowed)
__device__ float g_partial[(size_t)MAXGRID * CC]; // per-block column sums of p
__device__ float g_count[CC];                     // target histogram (float)
__device__ float g_conf[BB];                      // per-row max softmax prob = 1/Z
__device__ float g_cls, g_cal, g_crl;             // scalar accumulators

__device__ __forceinline__ float warp_max(float v) {
#pragma unroll
    for (int o = 16; o > 0; o >>= 1) v = fmaxf(v, __shfl_xor_sync(0xffffffffu, v, o));
    return v;
}
__device__ __forceinline__ float warp_sum(float v) {
#pragma unroll
    for (int o = 16; o > 0; o >>= 1) v += __shfl_xor_sync(0xffffffffu, v, o);
    return v;
}

__global__ void k0_zero() {
    int i = blockIdx.x * blockDim.x + threadIdx.x;
    if (i < CC) g_count[i] = 0.0f;
    if (i == 0) { g_cls = 0.0f; g_cal = 0.0f; g_crl = 0.0f; }
}

// Main kernel: persistent blocks, one 128KB row resident in SMEM at a time.
// Per row: (1) gmem->smem load tracking max, (2) exp in place + sumexp,
// (3) scale by 1/Z and accumulate per-class sums into registers.
__global__ __launch_bounds__(NT, 1) void k1_main(const float* __restrict__ logits,
                                                 const int* __restrict__ targets,
                                                 int ngrid) {
    extern __shared__ float4 srow[];   // NV4 float4 = 128000 bytes
    __shared__ float red[32];
    __shared__ float s_m, s_z, s_lt;

    const int tid  = threadIdx.x;
    const int lane = tid & 31;
    const int wid  = tid >> 5;

    float4 acc[KPT];
#pragma unroll
    for (int k = 0; k < KPT; k++) acc[k] = make_float4(0.f, 0.f, 0.f, 0.f);
    float local_cls = 0.0f;

    for (int row = blockIdx.x; row < BB; row += ngrid) {
        const float4* rp = reinterpret_cast<const float4*>(logits + (size_t)row * CC);
        const int tgt  = __ldg(targets + row);
        const int tgt4 = tgt >> 2, tgtc = tgt & 3;

        // ---- pass 1: stream row to SMEM, track max, capture target logit ----
        float tmax = __int_as_float(0xff800000); // -inf
#pragma unroll
        for (int k = 0; k < KPT; k++) {
            int j = tid + k * NT;
            if (j < NV4) {
                float4 v = __ldcs(rp + j); // streaming: evict-first
                srow[j] = v;
                tmax = fmaxf(fmaxf(fmaxf(v.x, v.y), fmaxf(v.z, v.w)), tmax);
                if (j == tgt4) {
                    s_lt = (tgtc == 0) ? v.x : ((tgtc == 1) ? v.y : ((tgtc == 2) ? v.z : v.w));
                }
            }
        }
        tmax = warp_max(tmax);
        if (lane == 0) red[wid] = tmax;
        __syncthreads();
        if (wid == 0) {
            float v = warp_max(red[lane]);
            if (lane == 0) s_m = v;
        }
        __syncthreads();
        const float m  = s_m;
        const float lt = s_lt;  // read into reg now (race-safe window)

        // ---- pass 2: exp in place, accumulate sumexp ----
        float tsum = 0.0f;
#pragma unroll
        for (int k = 0; k < KPT; k++) {
            int j = tid + k * NT;
            if (j < NV4) {
                float4 v = srow[j];
                float4 e;
                e.x = __expf(v.x - m); e.y = __expf(v.y - m);
                e.z = __expf(v.z - m); e.w = __expf(v.w - m);
                srow[j] = e;
                tsum += (e.x + e.y) + (e.z + e.w);
            }
        }
        tsum = warp_sum(tsum);
        if (lane == 0) red[wid] = tsum;
        __syncthreads();
        if (wid == 0) {
            float v = warp_sum(red[lane]);
            if (lane == 0) s_z = v;
        }
        __syncthreads();
        const float Z = s_z;
        const float invZ = 1.0f / Z;

        // ---- pass 3: accumulate per-class probability sums in registers ----
#pragma unroll
        for (int k = 0; k < KPT; k++) {
            int j = tid + k * NT;
            if (j < NV4) {
                float4 e = srow[j];
                acc[k].x += e.x * invZ; acc[k].y += e.y * invZ;
                acc[k].z += e.z * invZ; acc[k].w += e.w * invZ;
            }
        }

        if (tid == 0) {
            g_conf[row] = invZ;                       // max softmax prob
            local_cls += (logf(Z) + m - lt);          // -log p[target]
            atomicAdd(&g_count[tgt], 1.0f);           // target histogram
        }
        // No barrier needed before next row: srow slots are thread-private by
        // ownership; red/s_m/s_z/s_lt rewrites are separated by >=1 barrier.
    }

    // flush per-block column partials (coalesced float4 stores)
    float4* pp = reinterpret_cast<float4*>(g_partial) + (size_t)blockIdx.x * NV4;
#pragma unroll
    for (int k = 0; k < KPT; k++) {
        int j = tid + k * NT;
        if (j < NV4) pp[j] = acc[k];
    }
    if (tid == 0) atomicAdd(&g_cls, local_cls);
}

// MDCA: colsum over block partials, |colsum - count|, global sum.
__global__ void k2_mdca(int ngrid) {
    __shared__ float red[32];
    int c = blockIdx.x * blockDim.x + threadIdx.x;
    float s = 0.0f;
    if (c < CC) {
        float cs = 0.0f;
        for (int b = 0; b < ngrid; b++) cs += g_partial[(size_t)b * CC + c];
        s = fabsf(cs - g_count[c]);
    }
    s = warp_sum(s);
    int lane = threadIdx.x & 31, wid = threadIdx.x >> 5;
    if (lane == 0) red[wid] = s;
    __syncthreads();
    if (wid == 0) {
        s = (lane < (int)(blockDim.x >> 5)) ? red[lane] : 0.0f;
        s = warp_sum(s);
        if (lane == 0) atomicAdd(&g_cal, s);
    }
}

// CRL margin ranking loss over rolled pairs.
__global__ void k3_crl(const int* __restrict__ idx, const float* __restrict__ corr) {
    __shared__ float red[32];
    int b = blockIdx.x * blockDim.x + threadIdx.x;
    float s = 0.0f;
    if (b < BB) {
        int b2 = (b + 1) & (BB - 1);
        float conf1 = g_conf[b];
        float conf2 = g_conf[b2];
        float c1 = __ldg(corr + __ldg(idx + b));
        float c2 = __ldg(corr + __ldg(idx + b2));
        float d  = c1 - c2;
        float rt = (d > 0.f) ? 1.f : ((d < 0.f) ? -1.f : 0.f);
        float margin = fabsf(d);
        // margin / tnz == margin * tnz since tnz in {-1,+1}; rt==0 => margin==0
        float tnz = (rt == 0.f) ? 1.f : rt;
        float ri2 = conf2 + margin * tnz;
        s = fmaxf(0.f, -rt * (conf1 - ri2));
    }
    s = warp_sum(s);
    int lane = threadIdx.x & 31, wid = threadIdx.x >> 5;
    if (lane == 0) red[wid] = s;
    __syncthreads();
    if (wid == 0) {
        s = (lane < (int)(blockDim.x >> 5)) ? red[lane] : 0.0f;
        s = warp_sum(s);
        if (lane == 0) atomicAdd(&g_crl, s);
    }
}

__global__ void k4_final(float* out) {
    out[0] = g_cls * (1.0f / BB)
           + g_crl * (1.0f / BB)
           + g_cal * (1.0f / ((float)BB * (float)CC));
}

extern "C" void kernel_launch(void* const* d_in, const int* in_sizes, int n_in,
                              void* d_out, int out_size) {
    const float* logits  = (const float*)d_in[0];
    const int*   targets = (const int*)d_in[1];
    const int*   idx     = (const int*)d_in[2];
    const float* corr    = (const float*)d_in[3];
    float* out = (float*)d_out;

    int sm = 148;
    cudaDeviceGetAttribute(&sm, cudaDevAttrMultiProcessorCount, 0);
    int ngrid = sm < MAXGRID ? sm : MAXGRID;

    cudaFuncSetAttribute(k1_main, cudaFuncAttributeMaxDynamicSharedMemorySize,
                         NV4 * (int)sizeof(float4));

    k0_zero<<<(CC + 255) / 256, 256>>>();
    k1_main<<<ngrid, NT, NV4 * sizeof(float4)>>>(logits, targets, ngrid);
    k2_mdca<<<(CC + 255) / 256, 256>>>(ngrid);
    k3_crl<<<(BB + 255) / 256, 256>>>(idx, corr);
    k4_final<<<1, 1>>>(out);
}

// round 2
// speedup vs baseline: 1.2428x; 1.2428x over previous
#include <cuda_runtime.h>
#include <math.h>

#define BB 4096          // batch
#define CC 32000         // classes
#define NV4 8000         // float4 per row
#define NT 1024          // threads in main kernel
#define KPT 8            // float4 slots per thread
#define MAXGRID 160
#define NCALB 125        // MDCA blocks (32000/256)
#define NCRLB 4          // CRL blocks (4096/1024)

// Static device scratch (no zero-init required by design)
__device__ float g_partial[(size_t)MAXGRID * CC]; // per-block (colsum(p) - count)
__device__ float g_conf[BB];                      // per-row max softmax prob
__device__ float g_cls_arr[MAXGRID];              // per-block CE partial sums
__device__ float g_cal_arr[NCALB];                // per-block MDCA partials
__device__ float g_crl_arr[NCRLB];                // per-block CRL partials

__device__ __forceinline__ float warp_max(float v) {
#pragma unroll
    for (int o = 16; o > 0; o >>= 1) v = fmaxf(v, __shfl_xor_sync(0xffffffffu, v, o));
    return v;
}
__device__ __forceinline__ float warp_sum(float v) {
#pragma unroll
    for (int o = 16; o > 0; o >>= 1) v += __shfl_xor_sync(0xffffffffu, v, o);
    return v;
}

// ---------------------------------------------------------------------------
// k1: persistent blocks; one 125KB row in SMEM. Single fused streaming pass:
//   chunk loop: LDG row r  |  accumulate pass-3 of row r-1 from SMEM  |
//               e = exp(v) (no max shift)  |  STS e  |  track (max, sumexp)
//   then ONE block reduce (m, Z) per row. Pass-3 of the final row in epilogue.
// ---------------------------------------------------------------------------
__global__ __launch_bounds__(NT, 1) void k1_main(const float* __restrict__ logits,
                                                 const int* __restrict__ targets,
                                                 int ngrid) {
    extern __shared__ float4 srow[];   // 8000 float4 = 128000 B
    __shared__ float redm[32], redz[32];
    __shared__ float s_m, s_z, s_lt;

    const int tid  = threadIdx.x;
    const int lane = tid & 31;
    const int wid  = tid >> 5;

    float4 acc[KPT];
#pragma unroll
    for (int k = 0; k < KPT; k++) acc[k] = make_float4(0.f, 0.f, 0.f, 0.f);

    // zero SMEM so first-row pass-3 (invZp = 0) never hits NaN garbage
#pragma unroll
    for (int k = 0; k < KPT; k++) {
        int j = tid + k * NT;
        if (j < NV4) srow[j] = make_float4(0.f, 0.f, 0.f, 0.f);
    }
    __syncthreads();

    float local_cls = 0.0f;
    float invZp = 0.0f;               // 1/Z of previous row (0 = no previous row)

    for (int row = blockIdx.x; row < BB; row += ngrid) {
        const float4* rp = reinterpret_cast<const float4*>(logits + (size_t)row * CC);
        const int tgt  = __ldg(targets + row);
        const int tgt4 = tgt >> 2, tgtc = tgt & 3;

        float m_t = -1e30f;
        float z_t = 0.0f;

#pragma unroll
        for (int k = 0; k < KPT; k++) {
            int j = tid + k * NT;
            if (j < NV4) {
                float4 v  = __ldcs(rp + j);       // stream row r from gmem
                float4 eo = srow[j];              // row r-1 exp values
                acc[k].x = fmaf(eo.x, invZp, acc[k].x);   // pass-3 of row r-1
                acc[k].y = fmaf(eo.y, invZp, acc[k].y);
                acc[k].z = fmaf(eo.z, invZp, acc[k].z);
                acc[k].w = fmaf(eo.w, invZp, acc[k].w);
                float4 e;
                e.x = __expf(v.x); e.y = __expf(v.y);
                e.z = __expf(v.z); e.w = __expf(v.w);
                srow[j] = e;
                m_t = fmaxf(m_t, fmaxf(fmaxf(v.x, v.y), fmaxf(v.z, v.w)));
                z_t += (e.x + e.y) + (e.z + e.w);
                if (j == tgt4) {
                    s_lt = (tgtc == 0) ? v.x : ((tgtc == 1) ? v.y
                         : ((tgtc == 2) ? v.z : v.w));
                    // fold target histogram: MDCA uses (colsum(p) - count)
                    if (tgtc == 0) acc[k].x -= 1.0f;
                    else if (tgtc == 1) acc[k].y -= 1.0f;
                    else if (tgtc == 2) acc[k].z -= 1.0f;
                    else acc[k].w -= 1.0f;
                }
            }
        }

        // single joint (max, sum) block reduce
        float m = warp_max(m_t);
        float z = warp_sum(z_t);
        if (lane == 0) { redm[wid] = m; redz[wid] = z; }
        __syncthreads();
        if (wid == 0) {
            m = warp_max(redm[lane]);
            z = warp_sum(redz[lane]);
            if (lane == 0) { s_m = m; s_z = z; }
        }
        __syncthreads();
        const float Z = s_z;
        invZp = 1.0f / Z;
        if (tid == 0) {
            g_conf[row] = __expf(s_m) * invZp;    // max softmax prob
            local_cls += (logf(Z) - s_lt);        // -log p[target] (no shift)
        }
        __syncthreads();   // protect s_lt / red arrays before next row's writes
    }

    // epilogue: pass-3 for the last row this block processed
#pragma unroll
    for (int k = 0; k < KPT; k++) {
        int j = tid + k * NT;
        if (j < NV4) {
            float4 e = srow[j];
            acc[k].x = fmaf(e.x, invZp, acc[k].x);
            acc[k].y = fmaf(e.y, invZp, acc[k].y);
            acc[k].z = fmaf(e.z, invZp, acc[k].z);
            acc[k].w = fmaf(e.w, invZp, acc[k].w);
        }
    }

    // flush per-block column partials (coalesced float4 stores)
    float4* pp = reinterpret_cast<float4*>(g_partial) + (size_t)blockIdx.x * NV4;
#pragma unroll
    for (int k = 0; k < KPT; k++) {
        int j = tid + k * NT;
        if (j < NV4) pp[j] = acc[k];
    }
    if (tid == 0) g_cls_arr[blockIdx.x] = local_cls;
}

// ---------------------------------------------------------------------------
// k2: blocks 0..124 -> MDCA column reduce; blocks 125..128 -> CRL ranking loss
// ---------------------------------------------------------------------------
__global__ void k2_reduce(int ngrid, const int* __restrict__ idx,
                          const float* __restrict__ corr) {
    __shared__ float red[32];
    const int tid = threadIdx.x, lane = tid & 31, wid = tid >> 5;
    const int bid = blockIdx.x;
    float s = 0.0f;

    if (bid < NCALB) {
        int c = bid * 256 + tid;                  // c < 32000 always
        float cs = 0.0f;
        for (int b = 0; b < ngrid; b++) cs += g_partial[(size_t)b * CC + c];
        s = fabsf(cs);                            // |colsum(p) - count|
    } else {
        int base = (bid - NCALB) * 1024;
        for (int t = tid; t < 1024; t += 256) {
            int b  = base + t;
            int b2 = (b + 1) & (BB - 1);
            float conf1 = g_conf[b];
            float conf2 = g_conf[b2];
            float c1 = __ldg(corr + __ldg(idx + b));
            float c2 = __ldg(corr + __ldg(idx + b2));
            float d  = c1 - c2;
            float rt = (d > 0.f) ? 1.f : ((d < 0.f) ? -1.f : 0.f);
            float tnz = (rt == 0.f) ? 1.f : rt;
            float ri2 = conf2 + fabsf(d) * tnz;   // margin/tnz == margin*tnz
            s += fmaxf(0.f, -rt * (conf1 - ri2));
        }
    }

    s = warp_sum(s);
    if (lane == 0) red[wid] = s;
    __syncthreads();
    if (wid == 0) {
        s = (lane < 8) ? red[lane] : 0.0f;
        s = warp_sum(s);
        if (lane == 0) {
            if (bid < NCALB) g_cal_arr[bid] = s;
            else             g_crl_arr[bid - NCALB] = s;
        }
    }
}

// ---------------------------------------------------------------------------
// k3: final combine (no pre-zeroed accumulators anywhere)
// ---------------------------------------------------------------------------
__global__ void k3_final(float* __restrict__ out, int ngrid) {
    __shared__ float red[32];
    const int tid = threadIdx.x, lane = tid & 31, wid = tid >> 5;
    float cal = 0.f, cls = 0.f, crl = 0.f;
    for (int i = tid; i < NCALB; i += 256) cal += g_cal_arr[i];
    for (int i = tid; i < ngrid; i += 256) cls += g_cls_arr[i];
    if (tid < NCRLB) crl = g_crl_arr[tid];
    float tot = cls * (1.0f / BB) + crl * (1.0f / BB)
              + cal * (1.0f / ((float)BB * (float)CC));
    tot = warp_sum(tot);
    if (lane == 0) red[wid] = tot;
    __syncthreads();
    if (wid == 0) {
        tot = (lane < 8) ? red[lane] : 0.0f;
        tot = warp_sum(tot);
        if (lane == 0) out[0] = tot;
    }
}

extern "C" void kernel_launch(void* const* d_in, const int* in_sizes, int n_in,
                              void* d_out, int out_size) {
    const float* logits  = (const float*)d_in[0];
    const int*   targets = (const int*)d_in[1];
    const int*   idx     = (const int*)d_in[2];
    const float* corr    = (const float*)d_in[3];
    float* out = (float*)d_out;

    int sm = 148;
    cudaDeviceGetAttribute(&sm, cudaDevAttrMultiProcessorCount, 0);
    int ngrid = sm < MAXGRID ? sm : MAXGRID;

    cudaFuncSetAttribute(k1_main, cudaFuncAttributeMaxDynamicSharedMemorySize,
                         NV4 * (int)sizeof(float4));

    k1_main<<<ngrid, NT, NV4 * sizeof(float4)>>>(logits, targets, ngrid);
    k2_reduce<<<NCALB + NCRLB, 256>>>(ngrid, idx, corr);
    k3_final<<<1, 256>>>(out, ngrid);
}